// round 3
// baseline (speedup 1.0000x reference)
#include <cuda_runtime.h>
#include <cuda_fp16.h>
#include <stdint.h>

// RNNWithCheckpoint: T=512, B=128, H=1024, L=4 multi-layer tanh RNN.
// R1: single persistent kernel, custom grid barrier, SMEM-resident weights.
// Wavefront over layers: super-step s computes time t=s-l on layer l.
// fp16 MMA + fp32 accumulate; deterministic split-K via explicit partials.

#define T_STEPS 512
#define BATCH   128
#define HID     1024
#define LAYERS  4
#define NCTA    128

// SMEM (halves): padded rows to avoid bank conflicts on fragment LDS
#define SWROW 520   // 512 + 8   (weight slice, resident entire run)
#define SAROW 264   // 256 + 8   (activation chunk, reloaded per step)
#define SMEM_BYTES ((128 * SWROW + 128 * SAROW) * 2)   // 200704 B

// Static device scratch (no cudaMalloc allowed)
__device__ __half g_Wc[LAYERS * HID * 2048];   // [l][n][k2] k2<1024:Wih else Whh
__device__ float  g_bias[LAYERS * HID];        // b_ih + b_hh
__device__ __half g_act[LAYERS * BATCH * HID]; // per-layer outputs (fp16)
__device__ float  g_P[NCTA * 128 * 128];       // split-K partials [bx][b][n_local]
__device__ unsigned g_bar_count;
__device__ unsigned g_bar_epoch;

// ---------------------------------------------------------------- prep ----
__global__ void __launch_bounds__(256) prep_kernel(
    const float* __restrict__ Wih, const float* __restrict__ Whh,
    const float* __restrict__ bih, const float* __restrict__ bhh)
{
    int tid  = blockIdx.x * blockDim.x + threadIdx.x;
    int nthr = gridDim.x * blockDim.x;
    if (tid == 0) { g_bar_count = 0; g_bar_epoch = 0; }
    const int NW = LAYERS * HID * 2048;
    for (int i = tid; i < NW; i += nthr) {
        int k2 = i & 2047;
        int ln = i >> 11;  // l*1024 + n
        float v = (k2 < 1024) ? Wih[ln * 1024 + k2] : Whh[ln * 1024 + (k2 - 1024)];
        g_Wc[i] = __float2half(v);
    }
    for (int i = tid; i < LAYERS * HID; i += nthr) g_bias[i] = bih[i] + bhh[i];
    for (int i = tid; i < LAYERS * BATCH * HID; i += nthr) g_act[i] = __float2half(0.0f);
}

// ---------------------------------------------------------- grid barrier --
__device__ __forceinline__ void grid_barrier(unsigned target)
{
    __syncthreads();
    if (threadIdx.x == 0) {
        __threadfence();                       // publish our writes
        unsigned prev = atomicAdd(&g_bar_count, 1);
        if (prev == NCTA - 1) {
            g_bar_count = 0;                   // safe: nobody touches count
            __threadfence();                   // count reset before release
            atomicExch(&g_bar_epoch, target);
        } else {
            volatile unsigned* ep = &g_bar_epoch;
            while (*ep < target) { __nanosleep(40); }
        }
        __threadfence();                       // acquire others' writes
    }
    __syncthreads();
}

// ---------------------------------------------------------------- mma -----
__device__ __forceinline__ void mma16816(float* c, const uint32_t* a, const uint32_t* b)
{
    asm volatile(
        "mma.sync.aligned.m16n8k16.row.col.f32.f16.f16.f32 "
        "{%0,%1,%2,%3}, {%4,%5,%6,%7}, {%8,%9}, {%0,%1,%2,%3};"
        : "+f"(c[0]), "+f"(c[1]), "+f"(c[2]), "+f"(c[3])
        : "r"(a[0]), "r"(a[1]), "r"(a[2]), "r"(a[3]), "r"(b[0]), "r"(b[1]));
}

// ----------------------------------------------------------- persistent ---
// Grid: 128 CTAs = l(4) x ntile(8, N=128) x ksplit(4, K=512). Block: 256 thr.
__global__ void __launch_bounds__(256) rnn_persistent(
    const float* __restrict__ x, float* __restrict__ out)
{
    extern __shared__ __half sh[];
    __half* sW = sh;                  // [128][SWROW] resident weight slice
    __half* sA = sh + 128 * SWROW;    // [128][SAROW] activation chunk

    const int bx   = blockIdx.x;
    const int l    = bx >> 5;
    const int nt   = (bx >> 2) & 7;
    const int ks   = bx & 3;
    const int tid  = threadIdx.x;
    const int wid  = tid >> 5, lane = tid & 31;
    const int wm   = (wid >> 2) * 64;      // warp M offset (2 x 4 warp grid)
    const int wn   = (wid & 3) * 32;       // warp N offset
    const int g    = lane >> 2, tq = lane & 3;
    const int colbase = (ks & 1) * 512;

    // ---- load weight slice ONCE (stays in SMEM for all 512 steps)
    {
        const __half* wsrc = g_Wc + ((size_t)(l * HID + nt * 128) * 2048) + ks * 512;
        for (int i = tid; i < 128 * 64; i += 256) {
            int n = i >> 6, c = i & 63;
            *(int4*)&sW[n * SWROW + c * 8] = *(const int4*)&wsrc[(size_t)n * 2048 + c * 8];
        }
    }
    __syncthreads();

    unsigned bar = 0;

    for (int s = 0; s <= T_STEPS + LAYERS - 1; s++) {
        // ================= ACT phase: reduce step-(s-1) partials =========
        if (s >= 1) {
            int gtid = bx * 256 + tid;           // 0..32767, one 4-group each
            int b  = gtid >> 8;                  // batch row
            int ng = (gtid & 255) * 4;           // n start (multiple of 4)
            int ntg = ng >> 7, nl = ng & 127;
            #pragma unroll
            for (int ll = 0; ll < LAYERS; ll++) {
                int tprev = s - 1 - ll;
                if (tprev < 0 || tprev >= T_STEPS) continue;
                const float* Pb = g_P + ((size_t)(ll * 32 + ntg * 4) * 16384) + b * 128 + nl;
                float4 p0 = *(const float4*)(Pb);
                float4 p1 = *(const float4*)(Pb + 16384);
                float4 p2 = *(const float4*)(Pb + 2 * 16384);
                float4 p3 = *(const float4*)(Pb + 3 * 16384);
                float4 bs = *(const float4*)&g_bias[ll * HID + ng];
                float a0 = tanhf(bs.x + p0.x + p1.x + p2.x + p3.x);
                float a1 = tanhf(bs.y + p0.y + p1.y + p2.y + p3.y);
                float a2 = tanhf(bs.z + p0.z + p1.z + p2.z + p3.z);
                float a3 = tanhf(bs.w + p0.w + p1.w + p2.w + p3.w);
                size_t ai = (size_t)ll * BATCH * HID + b * HID + ng;
                *(__half2*)&g_act[ai]     = __floats2half2_rn(a0, a1);
                *(__half2*)&g_act[ai + 2] = __floats2half2_rn(a2, a3);
                if (ll == 3)
                    *(float4*)&out[(size_t)tprev * BATCH * HID + b * HID + ng] =
                        make_float4(a0, a1, a2, a3);
            }
        }
        grid_barrier(++bar);

        // ================= GEMM phase: partial[128x128] ==================
        int t = s - l;
        if (t >= 0 && t < T_STEPS) {
            // activation source: ks 0/1 -> layer input; ks 2/3 -> own h state
            const __half* asrc16 = nullptr;
            const float*  asrc32 = nullptr;
            if (ks < 2) {
                if (l == 0) asrc32 = x + (size_t)t * BATCH * HID;
                else        asrc16 = g_act + (size_t)(l - 1) * BATCH * HID;
            } else {
                asrc16 = g_act + (size_t)l * BATCH * HID;
            }

            float acc[4][4][4];
            #pragma unroll
            for (int i = 0; i < 4; i++)
                #pragma unroll
                for (int j = 0; j < 4; j++)
                    #pragma unroll
                    for (int k = 0; k < 4; k++) acc[i][j][k] = 0.0f;

            #pragma unroll
            for (int ch = 0; ch < 2; ch++) {
                int c0 = colbase + ch * 256;
                if (asrc32) {  // fp32 x -> fp16 on the fly
                    for (int i = tid; i < 128 * 64; i += 256) {
                        int r = i >> 6, c = i & 63;
                        float4 v = *(const float4*)&asrc32[(size_t)r * HID + c0 + c * 4];
                        *(__half2*)&sA[r * SAROW + c * 4]     = __floats2half2_rn(v.x, v.y);
                        *(__half2*)&sA[r * SAROW + c * 4 + 2] = __floats2half2_rn(v.z, v.w);
                    }
                } else {       // fp16 act
                    for (int i = tid; i < 128 * 32; i += 256) {
                        int r = i >> 5, c = i & 31;
                        *(int4*)&sA[r * SAROW + c * 8] =
                            *(const int4*)&asrc16[(size_t)r * HID + c0 + c * 8];
                    }
                }
                __syncthreads();

                int kwbase = ch * 256;
                #pragma unroll
                for (int kk = 0; kk < 16; kk++) {
                    int k16 = kk * 16;
                    uint32_t afrag[4][4];
                    #pragma unroll
                    for (int mt = 0; mt < 4; mt++) {
                        int r0 = wm + mt * 16 + g;
                        afrag[mt][0] = *(const uint32_t*)&sA[r0 * SAROW + k16 + tq * 2];
                        afrag[mt][1] = *(const uint32_t*)&sA[(r0 + 8) * SAROW + k16 + tq * 2];
                        afrag[mt][2] = *(const uint32_t*)&sA[r0 * SAROW + k16 + tq * 2 + 8];
                        afrag[mt][3] = *(const uint32_t*)&sA[(r0 + 8) * SAROW + k16 + tq * 2 + 8];
                    }
                    uint32_t bfrag[4][2];
                    #pragma unroll
                    for (int nti = 0; nti < 4; nti++) {
                        int n = wn + nti * 8 + g;
                        bfrag[nti][0] = *(const uint32_t*)&sW[n * SWROW + kwbase + k16 + tq * 2];
                        bfrag[nti][1] = *(const uint32_t*)&sW[n * SWROW + kwbase + k16 + tq * 2 + 8];
                    }
                    #pragma unroll
                    for (int mt = 0; mt < 4; mt++)
                        #pragma unroll
                        for (int nti = 0; nti < 4; nti++)
                            mma16816(acc[mt][nti], afrag[mt], bfrag[nti]);
                }
                __syncthreads();
            }

            // write split-K partial tile [128][128] fp32 (deterministic)
            float* P = g_P + (size_t)bx * 16384;
            #pragma unroll
            for (int mt = 0; mt < 4; mt++) {
                #pragma unroll
                for (int nti = 0; nti < 4; nti++) {
                    int r0 = wm + mt * 16 + g;
                    int c  = wn + nti * 8 + tq * 2;
                    *(float2*)&P[r0 * 128 + c] =
                        make_float2(acc[mt][nti][0], acc[mt][nti][1]);
                    *(float2*)&P[(r0 + 8) * 128 + c] =
                        make_float2(acc[mt][nti][2], acc[mt][nti][3]);
                }
            }
        }
        grid_barrier(++bar);
    }
}

// -------------------------------------------------------------- launch ----
extern "C" void kernel_launch(void* const* d_in, const int* in_sizes, int n_in,
                              void* d_out, int out_size)
{
    const float* x   = (const float*)d_in[0];
    const float* Wih = (const float*)d_in[1];
    const float* Whh = (const float*)d_in[2];
    const float* bih = (const float*)d_in[3];
    const float* bhh = (const float*)d_in[4];
    float* out = (float*)d_out;

    cudaFuncSetAttribute(rnn_persistent,
                         cudaFuncAttributeMaxDynamicSharedMemorySize, SMEM_BYTES);

    prep_kernel<<<256, 256>>>(Wih, Whh, bih, bhh);
    rnn_persistent<<<NCTA, 256, SMEM_BYTES>>>(x, out);
}

// round 5
// speedup vs baseline: 1.4801x; 1.4801x over previous
#include <cuda_runtime.h>
#include <cuda_fp16.h>
#include <stdint.h>

// RNNWithCheckpoint: T=512, B=128, H=1024, L=4 multi-layer tanh RNN.
// R3: persistent kernel, baseline-PTX tensor path (mma.sync m16n8k16 — the
// harness emits non-'a' PTX so tcgen05 is unavailable). 128 CTAs =
// 4 layers x 16 n-tiles(64) x 2 k-halves (ih|hh). Weights SMEM-resident.
// 2-way partial reduce via DSMEM inside a 2-CTA cluster; tanh fused into
// epilogue; ONE flag-array grid barrier per step; act parity-double-buffered.

#define T_STEPS 512
#define BATCH   128
#define HID     1024
#define LAYERS  4
#define NCTA    128

#define WROW 1032          // 1024 + 8 halves (bank-shift pad)
#define AROW 136           // 128 + 8 halves
#define SM_W  0            // 64 x WROW halves  = 132096 B
#define SM_A0 132096       // 128 x AROW halves = 34816 B
#define SM_A1 166912
#define SM_P  201728       // partial 64 x 68 fp32 = 17408 B
#define SMEM_BYTES 219136

// Static device scratch (no cudaMalloc allowed)
__device__ __align__(16) __half g_Wh[LAYERS * 2 * HID * HID];      // [l][ks][n][k]
__device__ __align__(16) __half g_xh[(size_t)T_STEPS * BATCH * HID];
__device__ __align__(16) float  g_bias[LAYERS * HID];
__device__ __align__(16) __half g_act[2][LAYERS * BATCH * HID];    // parity buffers
__device__ unsigned g_flags[NCTA * 32];

// ------------------------------------------------------------- helpers ----
__device__ __forceinline__ uint32_t smem_u32(const void* p) {
    uint32_t a;
    asm("{ .reg .u64 t; cvta.to.shared.u64 t, %1; cvt.u32.u64 %0, t; }"
        : "=r"(a) : "l"(p));
    return a;
}
__device__ __forceinline__ void cp16(uint32_t dst, const void* src) {
    asm volatile("cp.async.cg.shared.global [%0], [%1], 16;"
                 :: "r"(dst), "l"(src) : "memory");
}
__device__ __forceinline__ void cp_commit() {
    asm volatile("cp.async.commit_group;" ::: "memory");
}
__device__ __forceinline__ void ldsm4(uint32_t* r, uint32_t a) {
    asm volatile("ldmatrix.sync.aligned.m8n8.x4.shared.b16 {%0,%1,%2,%3}, [%4];"
                 : "=r"(r[0]), "=r"(r[1]), "=r"(r[2]), "=r"(r[3]) : "r"(a));
}
__device__ __forceinline__ void mma16816(float* c, const uint32_t* a,
                                         uint32_t b0, uint32_t b1) {
    asm volatile(
        "mma.sync.aligned.m16n8k16.row.col.f32.f16.f16.f32 "
        "{%0,%1,%2,%3}, {%4,%5,%6,%7}, {%8,%9}, {%0,%1,%2,%3};"
        : "+f"(c[0]), "+f"(c[1]), "+f"(c[2]), "+f"(c[3])
        : "r"(a[0]), "r"(a[1]), "r"(a[2]), "r"(a[3]), "r"(b0), "r"(b1));
}
__device__ __forceinline__ uint32_t mapa_u32(uint32_t a, uint32_t rk) {
    uint32_t o;
    asm("mapa.shared::cluster.u32 %0, %1, %2;" : "=r"(o) : "r"(a), "r"(rk));
    return o;
}
__device__ __forceinline__ float2 ld_dsmem2(uint32_t a) {
    float2 v;
    asm volatile("ld.shared::cluster.v2.f32 {%0,%1}, [%2];"
                 : "=f"(v.x), "=f"(v.y) : "r"(a) : "memory");
    return v;
}

// ---------------------------------------------------------------- prep ----
__global__ void __launch_bounds__(256) prep_kernel(
    const float* __restrict__ x,
    const float* __restrict__ Wih, const float* __restrict__ Whh,
    const float* __restrict__ bih, const float* __restrict__ bhh)
{
    int tid  = blockIdx.x * blockDim.x + threadIdx.x;
    int nthr = gridDim.x * blockDim.x;
    const int NW = LAYERS * HID * HID;
    for (int i = tid; i < NW; i += nthr) {
        int l  = i >> 20;                 // HID*HID = 2^20
        int nk = i & (HID * HID - 1);
        g_Wh[((size_t)(l * 2 + 0) << 20) + nk] = __float2half(Wih[i]);
        g_Wh[((size_t)(l * 2 + 1) << 20) + nk] = __float2half(Whh[i]);
    }
    const size_t NX4 = (size_t)T_STEPS * BATCH * HID / 4;
    for (size_t i = tid; i < NX4; i += nthr) {
        float4 v = *(const float4*)(x + i * 4);
        *(__half2*)&g_xh[i * 4]     = __floats2half2_rn(v.x, v.y);
        *(__half2*)&g_xh[i * 4 + 2] = __floats2half2_rn(v.z, v.w);
    }
    for (int i = tid; i < LAYERS * HID; i += nthr) g_bias[i] = bih[i] + bhh[i];
    for (int i = tid; i < LAYERS * BATCH * HID; i += nthr) {
        g_act[0][i] = __float2half(0.0f);
        g_act[1][i] = __float2half(0.0f);
    }
    for (int i = tid; i < NCTA * 32; i += nthr) g_flags[i] = 0;
}

// ---------------------------------------------------------- grid barrier --
__device__ __forceinline__ void grid_barrier(unsigned target, int bx)
{
    __syncthreads();
    if (threadIdx.x < 32) {
        if (threadIdx.x == 0) {
            __threadfence();
            atomicExch(&g_flags[bx * 32], target);
        }
        const volatile unsigned* f = g_flags;
        int i0 = threadIdx.x * 4;
        for (;;) {
            bool ok = (f[(i0 + 0) * 32] >= target) & (f[(i0 + 1) * 32] >= target) &
                      (f[(i0 + 2) * 32] >= target) & (f[(i0 + 3) * 32] >= target);
            if (__all_sync(0xffffffffu, ok)) break;
            __nanosleep(60);
        }
        __threadfence();
    }
    __syncthreads();
}

// ----------------------------------------------------------- persistent ---
// bx: l = bx>>5, nt = (bx>>1)&15, rank = bx&1 (cluster pair = the 2 k-halves).
// Each CTA: partial C[128 x 64] = A[128 x 1024] @ W[64 x 1024]^T, then
// DSMEM exchange within the pair, +bias, tanh, write act (+out for l=3).
__global__ void __launch_bounds__(256) __cluster_dims__(2, 1, 1)
rnn_persistent(float* __restrict__ out)
{
    extern __shared__ char sh[];
    const uint32_t sb = smem_u32(sh);

    const int bx   = blockIdx.x;
    const int l    = bx >> 5;
    const int nt   = (bx >> 1) & 15;
    const int rank = bx & 1;
    const int tid  = threadIdx.x;
    const int wid  = tid >> 5, lane = tid & 31;
    const int g    = lane >> 2, tq = lane & 3;
    const int wm   = (wid >> 1) * 32;   // 4 m-groups of 32 rows
    const int wn   = (wid & 1) * 32;    // 2 n-groups of 32 cols

    // ---- resident weight slice: 64 n-rows x 1024 k halves
    {
        const __half* wsrc = g_Wh + (((size_t)(l * 2 + rank) * HID) + nt * 64) * HID;
        for (int i = tid; i < 8192; i += 256) {
            int r = i >> 7, c = i & 127;
            cp16(sb + SM_W + (uint32_t)(r * WROW + c * 8) * 2,
                 wsrc + (size_t)r * HID + c * 8);
        }
        cp_commit();
        asm volatile("cp.async.wait_group 0;" ::: "memory");
        __syncthreads();
    }

    // per-thread constant addresses
    const uint32_t aoff = (uint32_t)(((wm + (lane & 15)) * AROW + (lane >> 4) * 8) * 2);
    uint32_t wb[2];
    #pragma unroll
    for (int p = 0; p < 2; p++)
        wb[p] = sb + SM_W +
                (uint32_t)(((wn + p * 16 + (lane & 15)) * WROW + (lane >> 4) * 8) * 2);
    float2 bs[4];
    #pragma unroll
    for (int nti = 0; nti < 4; nti++)
        bs[nti] = *(const float2*)&g_bias[l * HID + nt * 64 + wn + nti * 8 + tq * 2];

    const int  fin0 = rank * 64;
    const bool fin  = (rank == 0) ? (wm < 64) : (wm >= 64);
    float* sP = (float*)(sh + SM_P);

    unsigned bar = 0;

    #pragma unroll 1
    for (int s = 0; s <= T_STEPS + LAYERS - 1; s++) {
        const int t = s - l;
        const bool active = (t >= 0 && t < T_STEPS);
        if (active) {
            // A source: rank0 = layer input (x or act[l-1]); rank1 = own h
            const __half* src;
            const __half* actr = g_act[(s & 1) ^ 1];
            if (rank == 1)       src = actr + (size_t)l * BATCH * HID;
            else if (l == 0)     src = g_xh + (size_t)t * BATCH * HID;
            else                 src = actr + (size_t)(l - 1) * BATCH * HID;

            // prologue: chunks 0,1
            #pragma unroll
            for (int c0 = 0; c0 < 2; c0++) {
                uint32_t dst = sb + (c0 ? SM_A1 : SM_A0);
                const __half* sp = src + c0 * 128;
                for (int i = tid; i < 2048; i += 256) {
                    int r = i >> 4, c = i & 15;
                    cp16(dst + (uint32_t)(r * AROW + c * 8) * 2,
                         sp + (size_t)r * HID + c * 8);
                }
                cp_commit();
            }

            float acc[2][4][4];
            #pragma unroll
            for (int i = 0; i < 2; i++)
                #pragma unroll
                for (int j = 0; j < 4; j++)
                    #pragma unroll
                    for (int k = 0; k < 4; k++) acc[i][j][k] = 0.0f;

            #pragma unroll 2
            for (int ch = 0; ch < 8; ch++) {
                if (ch < 7) asm volatile("cp.async.wait_group 1;" ::: "memory");
                else        asm volatile("cp.async.wait_group 0;" ::: "memory");
                __syncthreads();

                uint32_t ab = sb + ((ch & 1) ? SM_A1 : SM_A0) + aoff;
                uint32_t kb = (uint32_t)(ch * 256);
                #pragma unroll
                for (int j = 0; j < 8; j++) {
                    uint32_t a0[4], a1[4], b0[4], b1[4];
                    ldsm4(a0, ab + j * 32);
                    ldsm4(a1, ab + 16 * AROW * 2 + j * 32);
                    ldsm4(b0, wb[0] + kb + j * 32);
                    ldsm4(b1, wb[1] + kb + j * 32);
                    mma16816(acc[0][0], a0, b0[0], b0[2]);
                    mma16816(acc[0][1], a0, b0[1], b0[3]);
                    mma16816(acc[0][2], a0, b1[0], b1[2]);
                    mma16816(acc[0][3], a0, b1[1], b1[3]);
                    mma16816(acc[1][0], a1, b0[0], b0[2]);
                    mma16816(acc[1][1], a1, b0[1], b0[3]);
                    mma16816(acc[1][2], a1, b1[0], b1[2]);
                    mma16816(acc[1][3], a1, b1[1], b1[3]);
                }
                __syncthreads();
                if (ch < 6) {   // refill this buffer with chunk ch+2
                    uint32_t dst = sb + ((ch & 1) ? SM_A1 : SM_A0);
                    const __half* sp = src + (ch + 2) * 128;
                    for (int i = tid; i < 2048; i += 256) {
                        int r = i >> 4, c = i & 15;
                        cp16(dst + (uint32_t)(r * AROW + c * 8) * 2,
                             sp + (size_t)r * HID + c * 8);
                    }
                    cp_commit();
                }
            }

            // ---- partial exchange within cluster pair
            if (!fin) {
                int nonfin0 = 64 - fin0;
                #pragma unroll
                for (int mt = 0; mt < 2; mt++) {
                    int rr = wm + mt * 16 + g - nonfin0;
                    #pragma unroll
                    for (int nti = 0; nti < 4; nti++) {
                        int c = wn + nti * 8 + tq * 2;
                        *(float2*)&sP[rr * 68 + c] =
                            make_float2(acc[mt][nti][0], acc[mt][nti][1]);
                        *(float2*)&sP[(rr + 8) * 68 + c] =
                            make_float2(acc[mt][nti][2], acc[mt][nti][3]);
                    }
                }
            }
            asm volatile("barrier.cluster.arrive.aligned;" ::: "memory");
            asm volatile("barrier.cluster.wait.aligned;" ::: "memory");

            if (fin) {
                uint32_t pp = mapa_u32(sb + SM_P, (uint32_t)(rank ^ 1));
                __half* actw = g_act[s & 1] + (size_t)l * BATCH * HID;
                #pragma unroll
                for (int mt = 0; mt < 2; mt++) {
                    int rg = wm + mt * 16 + g;
                    int rr = rg - fin0;
                    #pragma unroll
                    for (int nti = 0; nti < 4; nti++) {
                        int c  = wn + nti * 8 + tq * 2;
                        float2 p0 = ld_dsmem2(pp + (uint32_t)(rr * 68 + c) * 4);
                        float2 p1 = ld_dsmem2(pp + (uint32_t)((rr + 8) * 68 + c) * 4);
                        float v0 = tanhf(acc[mt][nti][0] + p0.x + bs[nti].x);
                        float v1 = tanhf(acc[mt][nti][1] + p0.y + bs[nti].y);
                        float v2 = tanhf(acc[mt][nti][2] + p1.x + bs[nti].x);
                        float v3 = tanhf(acc[mt][nti][3] + p1.y + bs[nti].y);
                        int cn = nt * 64 + c;
                        *(__half2*)&actw[(size_t)rg * HID + cn] =
                            __floats2half2_rn(v0, v1);
                        *(__half2*)&actw[(size_t)(rg + 8) * HID + cn] =
                            __floats2half2_rn(v2, v3);
                        if (l == 3) {
                            *(float2*)&out[(size_t)t * BATCH * HID + (size_t)rg * HID + cn] =
                                make_float2(v0, v1);
                            *(float2*)&out[(size_t)t * BATCH * HID + (size_t)(rg + 8) * HID + cn] =
                                make_float2(v2, v3);
                        }
                    }
                }
            }
        }
        grid_barrier(++bar, bx);
    }
}

// -------------------------------------------------------------- launch ----
extern "C" void kernel_launch(void* const* d_in, const int* in_sizes, int n_in,
                              void* d_out, int out_size)
{
    const float* x   = (const float*)d_in[0];
    const float* Wih = (const float*)d_in[1];
    const float* Whh = (const float*)d_in[2];
    const float* bih = (const float*)d_in[3];
    const float* bhh = (const float*)d_in[4];
    float* out = (float*)d_out;

    cudaFuncSetAttribute(rnn_persistent,
                         cudaFuncAttributeMaxDynamicSharedMemorySize, SMEM_BYTES);

    prep_kernel<<<2048, 256>>>(x, Wih, Whh, bih, bhh);
    rnn_persistent<<<NCTA, 256, SMEM_BYTES>>>(out);
}